// round 6
// baseline (speedup 1.0000x reference)
#include <cuda_runtime.h>
#include <cuda_bf16.h>

#define NBS   256   // B*S
#define LSEQ  128   // L
#define NA    8
#define NT    8
#define DIM   768   // D
#define CCH   128   // columns per tile
#define NCH   (DIM / CCH)      // 6
#define ROWF4 (DIM / 4)        // 192 float4 per row
#define NPAIR 24
#define NTILES (NBS * NCH)     // 1536
#define GRID  888              // 148 SMs * 6 CTAs

__device__ unsigned g_tile = 0;
__device__ unsigned g_done = 0;

__global__ __launch_bounds__(256, 6)
void slmuse_fused_kernel(const int* __restrict__ sentence_ids,
                         const int* __restrict__ attention_masks,
                         const int* __restrict__ predicate_ids,
                         const int* __restrict__ arg0_ids,
                         const int* __restrict__ arg1_ids,
                         const float* __restrict__ emb,
                         float* __restrict__ out)
{
    const int tid  = threadIdx.x;
    const int warp = tid >> 5;
    const int lane = tid & 31;
    const unsigned lmask = (1u << lane) - 1u;

    __shared__ int      s_sid[LSEQ];
    __shared__ float    s_mask[LSEQ];
    __shared__ int      s_ids[3][NA * NT];
    __shared__ float2   s_ent[NPAIR][LSEQ];  // x = int_bits(l*ROWF4), y = weight
    __shared__ int      s_nnz[NPAIR];
    __shared__ float    s_inv[NPAIR];
    __shared__ float    s_invmask;
    __shared__ float4   s_red[256];
    __shared__ unsigned s_tile;

    for (;;) {
        if (tid == 0) s_tile = atomicAdd(&g_tile, 1u);
        __syncthreads();
        const unsigned t = s_tile;
        if (t >= NTILES) break;

        const int bs    = (int)(t & (NBS - 1));   // bs-minor
        const int chunk = (int)(t >> 8);          // 0..5

        // ---- phase 0: ids / mask into smem ----
        if (tid < LSEQ) {
            s_sid[tid]  = sentence_ids[bs * LSEQ + tid];
            s_mask[tid] = (float)attention_masks[bs * LSEQ + tid];
        }
        if (tid < NA * NT) {
            s_ids[0][tid] = predicate_ids[bs * (NA * NT) + tid];
            s_ids[1][tid] = arg0_ids[bs * (NA * NT) + tid];
            s_ids[2][tid] = arg1_ids[bs * (NA * NT) + tid];
        }
        __syncthreads();

        // ---- phase 1: SIMD match (ids < 256 fit in bytes) + ballot compact ----
        // lane packs sid for l = lane, lane+32, lane+64, lane+96
        const unsigned sp = (unsigned)s_sid[lane]
                          | ((unsigned)s_sid[lane + 32] << 8)
                          | ((unsigned)s_sid[lane + 64] << 16)
                          | ((unsigned)s_sid[lane + 96] << 24);
#pragma unroll
        for (int r = 0; r < 3; r++) {
            const int j = warp + 8 * r;
            unsigned wq = 0;
#pragma unroll
            for (int tt = 0; tt < NT; tt++) {
                const int tok = s_ids[r][warp * NT + tt];
                const unsigned eq = __vcmpeq4(sp, (unsigned)tok * 0x01010101u);
                wq = __vadd4(wq, eq & (tok ? 0x01010101u : 0u));
            }
            int nz = 0;
            float cnt = 0.0f;
#pragma unroll
            for (int b = 0; b < 4; b++) {
                const int w = (int)((wq >> (8 * b)) & 0xffu);
                const unsigned m = __ballot_sync(0xffffffffu, w > 0);
                if (w > 0) {
                    const int pos = nz + __popc(m & lmask);
                    float2 e;
                    e.x = __int_as_float((lane + 32 * b) * ROWF4);
                    e.y = (float)w;
                    s_ent[j][pos] = e;
                }
                nz  += __popc(m);
                cnt += (float)w;
            }
#pragma unroll
            for (int off = 16; off; off >>= 1)
                cnt += __shfl_xor_sync(0xffffffffu, cnt, off);
            if (lane == 0) { s_nnz[j] = nz; s_inv[j] = 1.0f / fmaxf(cnt, 1.0f); }
        }
        if (warp == 0) {
            float c = s_mask[lane] + s_mask[lane + 32] + s_mask[lane + 64] + s_mask[lane + 96];
#pragma unroll
            for (int off = 16; off; off >>= 1)
                c += __shfl_xor_sync(0xffffffffu, c, off);
            if (lane == 0) s_invmask = 1.0f / fmaxf(c, 1.0f);
        }
        __syncthreads();

        const float4* ebase =
            (const float4*)(emb + (size_t)bs * LSEQ * DIM + chunk * CCH);

        // ---- phase 2: mean-pool partials. warp = 16-row group, lane = f4 col ----
        {
            float4 a0 = {0,0,0,0}, a1 = {0,0,0,0}, a2 = {0,0,0,0}, a3 = {0,0,0,0};
#pragma unroll
            for (int i = 0; i < 16; i += 4) {
                const int l0 = warp * 16 + i;
                const float4 v0 = ebase[(size_t)(l0 + 0) * ROWF4 + lane];
                const float4 v1 = ebase[(size_t)(l0 + 1) * ROWF4 + lane];
                const float4 v2 = ebase[(size_t)(l0 + 2) * ROWF4 + lane];
                const float4 v3 = ebase[(size_t)(l0 + 3) * ROWF4 + lane];
                const float m0 = s_mask[l0 + 0], m1 = s_mask[l0 + 1];
                const float m2 = s_mask[l0 + 2], m3 = s_mask[l0 + 3];
                a0.x += m0 * v0.x; a0.y += m0 * v0.y; a0.z += m0 * v0.z; a0.w += m0 * v0.w;
                a1.x += m1 * v1.x; a1.y += m1 * v1.y; a1.z += m1 * v1.z; a1.w += m1 * v1.w;
                a2.x += m2 * v2.x; a2.y += m2 * v2.y; a2.z += m2 * v2.z; a2.w += m2 * v2.w;
                a3.x += m3 * v3.x; a3.y += m3 * v3.y; a3.z += m3 * v3.z; a3.w += m3 * v3.w;
            }
            float4 s;
            s.x = (a0.x + a1.x) + (a2.x + a3.x);
            s.y = (a0.y + a1.y) + (a2.y + a3.y);
            s.z = (a0.z + a1.z) + (a2.z + a3.z);
            s.w = (a0.w + a1.w) + (a2.w + a3.w);
            s_red[tid] = s;
        }
        // no barrier: phase 3 depends only on phase-1 data (already synced)

        // ---- phase 3: arg embeddings via decoded float4 gathers ----
#pragma unroll
        for (int r = 0; r < 3; r++) {
            const int j = warp + 8 * r;
            float4 acc = {0,0,0,0};
            const int nz = s_nnz[j];
            for (int i = 0; i < nz; i++) {
                const float2 e   = s_ent[j][i];     // uniform across warp
                const int    off = __float_as_int(e.x);
                const float  w   = e.y;
                const float4 v = ebase[off + lane];
                acc.x += w * v.x; acc.y += w * v.y; acc.z += w * v.z; acc.w += w * v.w;
            }
            const float inv = s_inv[j];
            float4 o;
            o.x = acc.x * inv; o.y = acc.y * inv; o.z = acc.z * inv; o.w = acc.w * inv;
            float* op = out + NBS * DIM
                        + r * (NBS * NA * DIM)
                        + (bs * NA + warp) * DIM
                        + chunk * CCH;
            ((float4*)op)[lane] = o;
        }

        // ---- final cross-warp reduce for the mean pool ----
        __syncthreads();
        if (tid < 32) {
            float4 s = {0,0,0,0};
#pragma unroll
            for (int g = 0; g < 8; g++) {
                const float4 v = s_red[g * 32 + tid];
                s.x += v.x; s.y += v.y; s.z += v.z; s.w += v.w;
            }
            const float inv = s_invmask;
            float4 o; o.x = s.x * inv; o.y = s.y * inv; o.z = s.z * inv; o.w = s.w * inv;
            ((float4*)(out + bs * DIM + chunk * CCH))[tid] = o;
        }
        // loop top __syncthreads separates this tile's smem use from the next
    }

    // ---- self-reset of the work-stealing counter (graph-replayable) ----
    if (tid == 0) {
        const unsigned d = atomicAdd(&g_done, 1u);
        if (d == GRID - 1u) {          // last CTA: everyone has stopped fetching
            atomicExch(&g_tile, 0u);
            atomicExch(&g_done, 0u);
        }
    }
}

extern "C" void kernel_launch(void* const* d_in, const int* in_sizes, int n_in,
                              void* d_out, int out_size)
{
    const int*   sid  = (const int*)d_in[0];
    const int*   am   = (const int*)d_in[1];
    const int*   pred = (const int*)d_in[2];
    const int*   a0   = (const int*)d_in[3];
    const int*   a1   = (const int*)d_in[4];
    const float* emb  = (const float*)d_in[5];
    float* out = (float*)d_out;

    slmuse_fused_kernel<<<GRID, 256>>>(sid, am, pred, a0, a1, emb, out);
}

// round 7
// speedup vs baseline: 1.2793x; 1.2793x over previous
#include <cuda_runtime.h>
#include <cuda_bf16.h>

#define NBS   256   // B*S
#define LSEQ  128   // L
#define NA    8
#define NT    8
#define DIM   768   // D
#define CCH   256   // columns per CTA chunk
#define NCH   (DIM / CCH)   // 3
#define CF4   (CCH / 4)     // 64 float4 per chunk row
#define ROWF4 (DIM / 4)     // 192 float4 per full row
#define NPAIR 24

__global__ __launch_bounds__(256, 6)
void slmuse_fused_kernel(const int* __restrict__ sentence_ids,
                         const int* __restrict__ attention_masks,
                         const int* __restrict__ predicate_ids,
                         const int* __restrict__ arg0_ids,
                         const int* __restrict__ arg1_ids,
                         const float* __restrict__ emb,
                         float* __restrict__ out)
{
    const int bs    = blockIdx.x;    // 0..255
    const int chunk = blockIdx.y;    // 0..2
    const int tid   = threadIdx.x;
    const int warp  = tid >> 5;      // 0..7
    const int lane  = tid & 31;
    const unsigned lmask = (1u << lane) - 1u;

    __shared__ int    s_sid[LSEQ];
    __shared__ float  s_mask[LSEQ];
    __shared__ int    s_ids[3][NA * NT];
    __shared__ float2 s_ent[NPAIR][LSEQ];   // x = int_bits(l*ROWF4), y = weight
    __shared__ int    s_nnz[NPAIR];
    __shared__ float  s_inv[NPAIR];
    __shared__ float  s_invmask;
    __shared__ float4 s_red[256];

    // ---- phase 0: ids / mask into smem ----
    if (tid < LSEQ) {
        s_sid[tid]  = sentence_ids[bs * LSEQ + tid];
        s_mask[tid] = (float)attention_masks[bs * LSEQ + tid];
    }
    if (tid < NA * NT) {
        s_ids[0][tid] = predicate_ids[bs * (NA * NT) + tid];
        s_ids[1][tid] = arg0_ids[bs * (NA * NT) + tid];
        s_ids[2][tid] = arg1_ids[bs * (NA * NT) + tid];
    }
    __syncthreads();

    // ---- phase 1: SIMD match (ids < 256 fit in bytes) + ballot compact ----
    // lane packs sid for l = lane, lane+32, lane+64, lane+96
    const unsigned sp = (unsigned)s_sid[lane]
                      | ((unsigned)s_sid[lane + 32] << 8)
                      | ((unsigned)s_sid[lane + 64] << 16)
                      | ((unsigned)s_sid[lane + 96] << 24);
#pragma unroll
    for (int r = 0; r < 3; r++) {
        const int j = warp + 8 * r;
        unsigned wq = 0;
#pragma unroll
        for (int tt = 0; tt < NT; tt++) {
            const int tok = s_ids[r][warp * NT + tt];
            const unsigned eq = __vcmpeq4(sp, (unsigned)tok * 0x01010101u);
            wq = __vadd4(wq, eq & (tok ? 0x01010101u : 0u));
        }
        int nz = 0;
        float cnt = 0.0f;
#pragma unroll
        for (int b = 0; b < 4; b++) {
            const int w = (int)((wq >> (8 * b)) & 0xffu);
            const unsigned m = __ballot_sync(0xffffffffu, w > 0);
            if (w > 0) {
                const int pos = nz + __popc(m & lmask);
                float2 e;
                e.x = __int_as_float((lane + 32 * b) * ROWF4);
                e.y = (float)w;
                s_ent[j][pos] = e;
            }
            nz  += __popc(m);
            cnt += (float)w;
        }
#pragma unroll
        for (int off = 16; off; off >>= 1)
            cnt += __shfl_xor_sync(0xffffffffu, cnt, off);
        if (lane == 0) { s_nnz[j] = nz; s_inv[j] = 1.0f / fmaxf(cnt, 1.0f); }
    }
    if (warp == 0) {
        float c = s_mask[lane] + s_mask[lane + 32] + s_mask[lane + 64] + s_mask[lane + 96];
#pragma unroll
        for (int off = 16; off; off >>= 1)
            c += __shfl_xor_sync(0xffffffffu, c, off);
        if (lane == 0) s_invmask = 1.0f / fmaxf(c, 1.0f);
    }
    __syncthreads();

    const float4* ebase =
        (const float4*)(emb + (size_t)bs * LSEQ * DIM + chunk * CCH);

    // ---- phase 2: mean-pool partials. tid -> (f4 col 0..63, row-group of 32) ----
    {
        const int col = tid & (CF4 - 1);     // 0..63
        const int lg  = tid >> 6;            // 0..3 -> rows lg*32 .. lg*32+31
        const int l0b = lg * 32;
        float4 a0 = {0,0,0,0}, a1 = {0,0,0,0}, a2 = {0,0,0,0}, a3 = {0,0,0,0};
#pragma unroll
        for (int i = 0; i < 32; i += 4) {
            const int l0 = l0b + i;
            const float4 v0 = ebase[(size_t)(l0 + 0) * ROWF4 + col];
            const float4 v1 = ebase[(size_t)(l0 + 1) * ROWF4 + col];
            const float4 v2 = ebase[(size_t)(l0 + 2) * ROWF4 + col];
            const float4 v3 = ebase[(size_t)(l0 + 3) * ROWF4 + col];
            const float m0 = s_mask[l0 + 0], m1 = s_mask[l0 + 1];
            const float m2 = s_mask[l0 + 2], m3 = s_mask[l0 + 3];
            a0.x += m0 * v0.x; a0.y += m0 * v0.y; a0.z += m0 * v0.z; a0.w += m0 * v0.w;
            a1.x += m1 * v1.x; a1.y += m1 * v1.y; a1.z += m1 * v1.z; a1.w += m1 * v1.w;
            a2.x += m2 * v2.x; a2.y += m2 * v2.y; a2.z += m2 * v2.z; a2.w += m2 * v2.w;
            a3.x += m3 * v3.x; a3.y += m3 * v3.y; a3.z += m3 * v3.z; a3.w += m3 * v3.w;
        }
        float4 s;
        s.x = (a0.x + a1.x) + (a2.x + a3.x);
        s.y = (a0.y + a1.y) + (a2.y + a3.y);
        s.z = (a0.z + a1.z) + (a2.z + a3.z);
        s.w = (a0.w + a1.w) + (a2.w + a3.w);
        s_red[tid] = s;
    }
    // no barrier yet: phase 3 depends only on phase-1 data (already synced)

    // ---- phase 3: arg embeddings; each lane covers f4 cols lane and lane+32 ----
#pragma unroll
    for (int r = 0; r < 3; r++) {
        const int j = warp + 8 * r;
        float4 acc0 = {0,0,0,0}, acc1 = {0,0,0,0};
        const int nz = s_nnz[j];
        for (int i = 0; i < nz; i++) {
            const float2 e   = s_ent[j][i];      // uniform across warp
            const int    off = __float_as_int(e.x);
            const float  w   = e.y;
            const float4 v0 = ebase[off + lane];
            const float4 v1 = ebase[off + lane + 32];
            acc0.x += w * v0.x; acc0.y += w * v0.y; acc0.z += w * v0.z; acc0.w += w * v0.w;
            acc1.x += w * v1.x; acc1.y += w * v1.y; acc1.z += w * v1.z; acc1.w += w * v1.w;
        }
        const float inv = s_inv[j];
        float* op = out + NBS * DIM
                    + r * (NBS * NA * DIM)
                    + (bs * NA + warp) * DIM
                    + chunk * CCH;
        float4 o0, o1;
        o0.x = acc0.x * inv; o0.y = acc0.y * inv; o0.z = acc0.z * inv; o0.w = acc0.w * inv;
        o1.x = acc1.x * inv; o1.y = acc1.y * inv; o1.z = acc1.z * inv; o1.w = acc1.w * inv;
        ((float4*)op)[lane]      = o0;
        ((float4*)op)[lane + 32] = o1;
    }

    // ---- final cross-group reduce for the mean pool ----
    __syncthreads();
    if (tid < CF4) {
        float4 s = {0,0,0,0};
#pragma unroll
        for (int g = 0; g < 4; g++) {
            const float4 v = s_red[g * CF4 + tid];
            s.x += v.x; s.y += v.y; s.z += v.z; s.w += v.w;
        }
        const float inv = s_invmask;
        float4 o; o.x = s.x * inv; o.y = s.y * inv; o.z = s.z * inv; o.w = s.w * inv;
        ((float4*)(out + bs * DIM + chunk * CCH))[tid] = o;
    }
}

extern "C" void kernel_launch(void* const* d_in, const int* in_sizes, int n_in,
                              void* d_out, int out_size)
{
    const int*   sid  = (const int*)d_in[0];
    const int*   am   = (const int*)d_in[1];
    const int*   pred = (const int*)d_in[2];
    const int*   a0   = (const int*)d_in[3];
    const int*   a1   = (const int*)d_in[4];
    const float* emb  = (const float*)d_in[5];
    float* out = (float*)d_out;

    dim3 grid(NBS, NCH);   // 256 x 3 = 768 CTAs -> single wave at 6 CTAs/SM
    slmuse_fused_kernel<<<grid, 256>>>(sid, am, pred, a0, a1, emb, out);
}